// round 8
// baseline (speedup 1.0000x reference)
#include <cuda_runtime.h>

#define BATCH 4096
#define SEQT  256
#define DIN   32
#define HID   64
#define GATES 256
#define BT    32
#define NTHR  512
#define NCTA  128
#define ST    36    // padded row stride (floats) for transposed activation buffers

typedef unsigned long long u64;

// ---- global scratch (transposed weights, fused biases) — R1-proven layout ----
__device__ __align__(16) float g_W0t[HID * GATES];     // Whh0^T [64][256]
__device__ __align__(16) float g_Wx0t[DIN * GATES];    // Wih0^T [32][256] (per-step LDG)
__device__ __align__(16) float g_W1t[2 * HID * GATES]; // [Wih1; Whh1]^T [128][256]
__device__ __align__(16) float g_b0[GATES];
__device__ __align__(16) float g_b1[GATES];

__global__ void prep_kernel(const float* __restrict__ Wih0, const float* __restrict__ Whh0,
                            const float* __restrict__ bih0, const float* __restrict__ bhh0,
                            const float* __restrict__ Wih1, const float* __restrict__ Whh1,
                            const float* __restrict__ bih1, const float* __restrict__ bhh1)
{
    int idx = blockIdx.x * blockDim.x + threadIdx.x;
    int total = HID * GATES + DIN * GATES + 2 * HID * GATES + 2 * GATES;
    for (int i = idx; i < total; i += gridDim.x * blockDim.x) {
        if (i < HID * GATES) {
            int k = i / GATES, n = i % GATES;
            g_W0t[i] = Whh0[n * HID + k];
        } else if (i < HID * GATES + DIN * GATES) {
            int j = i - HID * GATES;
            int k = j / GATES, n = j % GATES;
            g_Wx0t[j] = Wih0[n * DIN + k];
        } else if (i < HID * GATES + DIN * GATES + 2 * HID * GATES) {
            int j = i - HID * GATES - DIN * GATES;
            int k = j / GATES, n = j % GATES;
            g_W1t[j] = (k < HID) ? Wih1[n * HID + k] : Whh1[n * HID + (k - HID)];
        } else {
            int j = i - (HID * GATES + DIN * GATES + 2 * HID * GATES);
            if (j < GATES) g_b0[j] = bih0[j] + bhh0[j];
            else           g_b1[j - GATES] = bih1[j - GATES] + bhh1[j - GATES];
        }
    }
}

// ---- packed f32x2 helpers ----
__device__ __forceinline__ u64 fma2(u64 a, u64 b, u64 c) {
    u64 d;
    asm("fma.rn.f32x2 %0, %1, %2, %3;" : "=l"(d) : "l"(a), "l"(b), "l"(c));
    return d;
}
__device__ __forceinline__ u64 add2(u64 a, u64 b) {
    u64 d;
    asm("add.rn.f32x2 %0, %1, %2;" : "=l"(d) : "l"(a), "l"(b));
    return d;
}
__device__ __forceinline__ u64 dup2(float x) {
    u64 d;
    asm("mov.b64 %0, {%1, %1};" : "=l"(d) : "f"(x));
    return d;
}
__device__ __forceinline__ float2 unpack2(u64 v) {
    float2 f;
    asm("mov.b64 {%0, %1}, %2;" : "=f"(f.x), "=f"(f.y) : "l"(v));
    return f;
}

// ---- fast activations (MUFU EX2/RCP, proven 2.5e-7 end-to-end) ----
__device__ __forceinline__ float fast_ex2(float x) {
    float y; asm("ex2.approx.f32 %0, %1;" : "=f"(y) : "f"(x)); return y;
}
__device__ __forceinline__ float fast_rcp(float x) {
    float y; asm("rcp.approx.f32 %0, %1;" : "=f"(y) : "f"(x)); return y;
}
__device__ __forceinline__ float sigf(float x) {
    return fast_rcp(1.0f + fast_ex2(-1.4426950408889634f * x));
}
__device__ __forceinline__ float tanhf_fast(float x) {
    x = fminf(fmaxf(x, -15.0f), 15.0f);
    float e = fast_ex2(-2.8853900817779268f * x);  // exp(-2x)
    return (1.0f - e) * fast_rcp(1.0f + e);
}

// GEMM fragment (R1 layout): acc[m][g] += inT[k][m0..m0+3] * Wt[k][g*64+u0..+1]
template <bool GLOBAL_W, int K>
__device__ __forceinline__ void gemm_part(const float* __restrict__ inT,
                                          const float* __restrict__ Wt,
                                          int m0, int u0, u64 acc[4][4])
{
#pragma unroll 4
    for (int k = 0; k < K; k++) {
        float4 hv = *(const float4*)(inT + k * ST + m0);
        u64 w[4];
#pragma unroll
        for (int g = 0; g < 4; g++) {
            const float* wp = Wt + k * GATES + g * HID + u0;
            if (GLOBAL_W) w[g] = __ldg((const u64*)wp);
            else          w[g] = *(const u64*)wp;
        }
        u64 a;
        a = dup2(hv.x);
#pragma unroll
        for (int g = 0; g < 4; g++) acc[0][g] = fma2(a, w[g], acc[0][g]);
        a = dup2(hv.y);
#pragma unroll
        for (int g = 0; g < 4; g++) acc[1][g] = fma2(a, w[g], acc[1][g]);
        a = dup2(hv.z);
#pragma unroll
        for (int g = 0; g < 4; g++) acc[2][g] = fma2(a, w[g], acc[2][g]);
        a = dup2(hv.w);
#pragma unroll
        for (int g = 0; g < 4; g++) acc[3][g] = fma2(a, w[g], acc[3][g]);
    }
}

// bias init: ks==0 lane carries the bias, ks==1 lane carries zero (added once on reduce)
__device__ __forceinline__ void acc_init(const float* __restrict__ sB, int u0, int ks,
                                         u64 acc[4][4])
{
#pragma unroll
    for (int g = 0; g < 4; g++) {
        u64 bp = ks ? 0ull : *(const u64*)(&sB[g * HID + u0]);
        acc[0][g] = bp; acc[1][g] = bp; acc[2][g] = bp; acc[3][g] = bp;
    }
}

// combine k-split halves across lane pairs (l <-> l^16)
__device__ __forceinline__ void reduce_half(const u64 acc[4][4], int ks, u64 s[2][4])
{
#pragma unroll
    for (int r = 0; r < 2; r++) {
#pragma unroll
        for (int g = 0; g < 4; g++) {
            u64 send = ks ? acc[r][g] : acc[r + 2][g];
            u64 got  = __shfl_xor_sync(0xffffffffu, send, 16);
            u64 mine = ks ? acc[r + 2][g] : acc[r][g];
            s[r][g] = add2(mine, got);
        }
    }
}

// update 2 rows x 2 cells; rows = m0 + 2*ks + {0,1}
__device__ __forceinline__ void lstm_update_half(const u64 s[2][4], float c[2][2],
                                                 float* __restrict__ hT,
                                                 int m0, int u0, int ks)
{
    float h[2][2];
#pragma unroll
    for (int r = 0; r < 2; r++) {
        float2 pi = unpack2(s[r][0]);
        float2 pf = unpack2(s[r][1]);
        float2 pg = unpack2(s[r][2]);
        float2 po = unpack2(s[r][3]);
        {
            float iv = sigf(pi.x), fv = sigf(pf.x), gv = tanhf_fast(pg.x), ov = sigf(po.x);
            float cc = fv * c[r][0] + iv * gv;
            c[r][0] = cc;
            h[r][0] = ov * tanhf_fast(cc);
        }
        {
            float iv = sigf(pi.y), fv = sigf(pf.y), gv = tanhf_fast(pg.y), ov = sigf(po.y);
            float cc = fv * c[r][1] + iv * gv;
            c[r][1] = cc;
            h[r][1] = ov * tanhf_fast(cc);
        }
    }
    const int mb = m0 + 2 * ks;
    *(float2*)(hT + (u0 + 0) * ST + mb) = make_float2(h[0][0], h[1][0]);
    *(float2*)(hT + (u0 + 1) * ST + mb) = make_float2(h[0][1], h[1][1]);
}

// Shared layout (floats)
#define OFF_W0   0
#define OFF_W1   (OFF_W0 + HID * GATES)
#define OFF_B0   (OFF_W1 + 2 * HID * GATES)
#define OFF_B1   (OFF_B0 + GATES)
#define OFF_H0T  (OFF_B1 + GATES)
#define OFF_H1T  (OFF_H0T + HID * ST)
#define OFF_XT   (OFF_H1T + HID * ST)
#define SMEM_FLOATS (OFF_XT + DIN * ST)

__global__ void __launch_bounds__(NTHR, 1)
lstm_fused(const float* __restrict__ x,
           const float* __restrict__ W1h, const float* __restrict__ b1h,
           const float* __restrict__ W2h, const float* __restrict__ b2h,
           float* __restrict__ out)
{
    extern __shared__ float sm[];
    float* sW0 = sm + OFF_W0;              // Whh0^T
    float* sW1 = sm + OFF_W1;              // [Wih1;Whh1]^T
    float* sB0 = sm + OFF_B0;
    float* sB1 = sm + OFF_B1;
    float* h0T = sm + OFF_H0T;
    float* h1T = sm + OFF_H1T;
    float* xT  = sm + OFF_XT;

    const int tid = threadIdx.x;
    const int b0  = blockIdx.x * BT;

    // stage weights + zero states
    for (int i = tid; i < HID * GATES / 4; i += NTHR)
        ((float4*)sW0)[i] = ((const float4*)g_W0t)[i];
    for (int i = tid; i < 2 * HID * GATES / 4; i += NTHR)
        ((float4*)sW1)[i] = ((const float4*)g_W1t)[i];
    if (tid < GATES) { sB0[tid] = g_b0[tid]; sB1[tid] = g_b1[tid]; }
    for (int i = tid; i < 2 * HID * ST; i += NTHR) h0T[i] = 0.0f;  // h0T+h1T contiguous

    // pair-split mapping: (warp, lane%16) -> tile; lane/16 -> k-half
    const int lane = tid & 31;
    const int ks   = lane >> 4;                      // 0 or 1
    const int idx  = (tid >> 5) * 16 + (lane & 15);  // 0..255
    const int gm   = idx & 7;
    const int gn   = idx >> 3;
    const int m0   = gm * 4;
    const int u0   = gn * 2;

    float c0[2][2] = {{0.f, 0.f}, {0.f, 0.f}};
    float c1[2][2] = {{0.f, 0.f}, {0.f, 0.f}};
    u64 acc0[4][4], acc1[4][4];
    u64 s0[2][4], s1[2][4];

    // pre-offset pointers for this thread's k-half
    const float* h0T_k = h0T + ks * 32 * ST;
    const float* h1T_k = h1T + ks * 32 * ST;
    const float* xT_k  = xT  + ks * 16 * ST;
    const float* sW0_k = sW0 + ks * 32 * GATES;
    const float* sW1a_k = sW1 + ks * 32 * GATES;                 // Wih1 half
    const float* sW1b_k = sW1 + HID * GATES + ks * 32 * GATES;   // Whh1 half
    const float* gWx_k = g_Wx0t + ks * 16 * GATES;

    // x staging: thread -> (row xm, float2 chunk xd)
    const int xm = tid >> 4;
    const int xd = tid & 15;
    const float* xrow = x + (size_t)(b0 + xm) * SEQT * DIN + xd * 2;

    // prologue: stage x(0); acc0 = b0 + Wih0*x(0) (h0(-1)=0)
    float2 xv = *(const float2*)(xrow);
    xT[(2 * xd + 0) * ST + xm] = xv.x;
    xT[(2 * xd + 1) * ST + xm] = xv.y;
    __syncthreads();

    acc_init(sB0, u0, ks, acc0);
    gemm_part<true, 16>(xT_k, gWx_k, m0, u0, acc0);
    xv = *(const float2*)(xrow + DIN);        // x(1)
    __syncthreads();                          // xT readers done before restage

    for (int t = 0; t < SEQT; t++) {
        // ---- P1: reduce+update0(t) (SHFL/MUFU) || Whh1*h1(t-1) (FFMA) + stage x(t+1)
        reduce_half(acc0, ks, s0);
        acc_init(sB1, u0, ks, acc1);
        gemm_part<false, 32>(h1T_k, sW1b_k, m0, u0, acc1);   // Whh1*h1(t-1)
        lstm_update_half(s0, c0, h0T, m0, u0, ks);           // writes h0(t)
        xT[(2 * xd + 0) * ST + xm] = xv.x;                   // stage x(t+1)
        xT[(2 * xd + 1) * ST + xm] = xv.y;
        {
            int tn = (t + 2 < SEQT) ? t + 2 : SEQT - 1;
            xv = *(const float2*)(xrow + (size_t)tn * DIN);  // prefetch x(t+2)
        }
        __syncthreads();                                     // B1: h0(t), x(t+1) visible

        // ---- P2: Wih1*h0(t) + Whh0*h0(t) + Wih0*x(t+1)  (pure FFMA)
        gemm_part<false, 32>(h0T_k, sW1a_k, m0, u0, acc1);   // Wih1*h0(t)
        if (t + 1 < SEQT) {
            acc_init(sB0, u0, ks, acc0);
            gemm_part<false, 32>(h0T_k, sW0_k, m0, u0, acc0);   // Whh0*h0(t)
            gemm_part<true, 16>(xT_k, gWx_k, m0, u0, acc0);     // Wih0*x(t+1)
        }

        // ---- P3: reduce+update1(t) (SHFL/MUFU), overlaps other warps' P2
        reduce_half(acc1, ks, s1);
        lstm_update_half(s1, c1, h1T, m0, u0, ks);           // writes h1(t)
        __syncthreads();                                     // B2: h1(t) visible
    }

    // ---- head: out[m] = b2 + sum_n W2[n]*relu(b1[n] + sum_k h1(k,m) W1[n,k]) ----
    {
        int m = tid >> 4;      // 0..31
        int q = tid & 15;      // 0..15
        float pm = 0.0f;
#pragma unroll
        for (int jj = 0; jj < 4; jj++) {
            int n = q * 4 + jj;
            float s = b1h[n];
#pragma unroll 8
            for (int k = 0; k < HID; k++)
                s += h1T[k * ST + m] * W1h[n * HID + k];
            pm += fmaxf(s, 0.0f) * W2h[n];
        }
#pragma unroll
        for (int off = 8; off > 0; off >>= 1)
            pm += __shfl_down_sync(0xffffffffu, pm, off, 16);
        if (q == 0) out[b0 + m] = pm + b2h[0];
    }
}

extern "C" void kernel_launch(void* const* d_in, const int* in_sizes, int n_in,
                              void* d_out, int out_size)
{
    const float* x    = (const float*)d_in[0];
    const float* Wih0 = (const float*)d_in[1];
    const float* Whh0 = (const float*)d_in[2];
    const float* bih0 = (const float*)d_in[3];
    const float* bhh0 = (const float*)d_in[4];
    const float* Wih1 = (const float*)d_in[5];
    const float* Whh1 = (const float*)d_in[6];
    const float* bih1 = (const float*)d_in[7];
    const float* bhh1 = (const float*)d_in[8];
    const float* W1   = (const float*)d_in[9];
    const float* b1   = (const float*)d_in[10];
    const float* W2   = (const float*)d_in[11];
    const float* b2   = (const float*)d_in[12];

    prep_kernel<<<64, 256>>>(Wih0, Whh0, bih0, bhh0, Wih1, Whh1, bih1, bhh1);

    size_t smem_bytes = (size_t)SMEM_FLOATS * sizeof(float);  // 221696 B
    cudaFuncSetAttribute(lstm_fused,
                         cudaFuncAttributeMaxDynamicSharedMemorySize, (int)smem_bytes);
    lstm_fused<<<NCTA, NTHR, smem_bytes>>>(x, W1, b1, W2, b2, (float*)d_out);
}